// round 14
// baseline (speedup 1.0000x reference)
#include <cuda_runtime.h>
#include <math.h>
#include <stdint.h>

#define TT 4
#define BB 16
#define CC 512
#define NN 1024
#define NHEADS 8
#define LCAP 48   // staged list cap (mean ~18, binomial std ~4.2 -> 7 sigma)

// ---------------- device scratch (no allocations allowed) ----------------
__device__ float g_Wp[CC * CC];            // [c][d], BN-folded proj
__device__ float g_bqk[1024];              // [0..511]=q bias, [512..1023]=k bias
__device__ float g_bp[CC];
// per-head weight slices, layout [h][c][e] with e=2*l+j <-> channel 64h + l + 32j
__device__ float g_Wq2[NHEADS * CC * 64];  // 1 MB
__device__ float g_Wk2[NHEADS * CC * 64];  // 1 MB
__device__ unsigned g_xs_cmask[TT * BB * NN * 16];
__device__ unsigned g_y_cmask[TT * BB * NN * 16];
// per-column active-channel list: entries from index 0 (4B-aligned), count separate
__device__ unsigned short g_listc[TT * BB * NN * 128];  // 16 MB
__device__ int g_cntc[TT * BB * NN];                    // 256 KB
__device__ unsigned char g_attn_b[NHEADS * TT * BB * NN];
__device__ float g_attn_fallback[TT * BB * NHEADS * NN];

// smem layout for q/k kernels
#define SM_W_BYTES   131072
#define SM_L_BYTES   (512 * LCAP * 2)          // 49152
#define SM_C_BYTES   2048
#define SMEM_QK_SZ   (SM_W_BYTES + SM_L_BYTES + SM_C_BYTES)   // 182272

// ---------------- K0a: fold BN into proj weights + biases ----------------
__global__ void prep_kernel(const float* __restrict__ qg, const float* __restrict__ qb,
                            const float* __restrict__ qm, const float* __restrict__ qv,
                            const float* __restrict__ kg, const float* __restrict__ kb,
                            const float* __restrict__ km, const float* __restrict__ kv,
                            const float* __restrict__ pw, const float* __restrict__ pbias,
                            const float* __restrict__ pg, const float* __restrict__ pb,
                            const float* __restrict__ pm, const float* __restrict__ pv) {
    int idx = blockIdx.x * blockDim.x + threadIdx.x;  // 512*512
    int d = idx & 511;
    int c = idx >> 9;
    float invp = (float)((double)pg[d] / sqrt((double)pv[d] + 1e-5));
    g_Wp[c * CC + d] = pw[d * CC + c] * invp;
    if (c == 0) {
        float invq = (float)((double)qg[d] / sqrt((double)qv[d] + 1e-5));
        float invk = (float)((double)kg[d] / sqrt((double)kv[d] + 1e-5));
        g_bqk[d]       = qb[d] - qm[d] * invq;
        g_bqk[512 + d] = kb[d] - km[d] * invk;
        g_bp[d]        = pbias[d] * invp + pb[d] - pm[d] * invp;
    }
}

// ---------------- K0b: per-head q/k weight slices, BN-folded -------------
__global__ __launch_bounds__(512) void prep_w2_kernel(
        const float* __restrict__ qw, const float* __restrict__ qg, const float* __restrict__ qv,
        const float* __restrict__ kw, const float* __restrict__ kg, const float* __restrict__ kv) {
    int idx = blockIdx.x * blockDim.x + threadIdx.x;  // 262144
    int e = idx & 63;
    int c = (idx >> 6) & 511;
    int h = idx >> 15;
    int d = 64 * h + (e >> 1) + 32 * (e & 1);
    float invq = (float)((double)qg[d] / sqrt((double)qv[d] + 1e-5));
    float invk = (float)((double)kg[d] / sqrt((double)kv[d] + 1e-5));
    g_Wq2[idx] = qw[d * CC + c] * invq;
    g_Wk2[idx] = kw[d * CC + c] * invk;
}

// ---------------- K1: LIF over x, pack channel bitmasks ----------------
__global__ __launch_bounds__(1024) void lif_x_kernel(const float* __restrict__ x) {
    int tid = threadIdx.x;
    int bid = blockIdx.x;
    int nblk = bid & 31;
    int cblk = (bid >> 5) & 15;
    int b = bid >> 9;
    int c_l = tid >> 5, n_l = tid & 31;
    int c = cblk * 32 + c_l;
    int n = nblk * 32 + n_l;
    __shared__ unsigned sw[32];
    const float* xp = x + ((size_t)b * CC + c) * NN + n;
    // prefetch all 4 timesteps (independent coalesced LDGs -> MLP=4)
    float xv[TT];
#pragma unroll
    for (int t = 0; t < TT; t++) xv[t] = xp[(size_t)t * BB * CC * NN];
    float v = 0.f;
#pragma unroll
    for (int t = 0; t < TT; t++) {
        v = v + (xv[t] - v) * 0.5f;
        bool s = (v >= 1.0f);
        if (s) v = 0.f;
        unsigned bm = __ballot_sync(0xffffffffu, s);
        if (n_l == 0) sw[c_l] = bm;
        __syncthreads();
        int n2 = tid >> 5, c2 = tid & 31;
        bool bit = (sw[c2] >> n2) & 1u;
        unsigned cword = __ballot_sync(0xffffffffu, bit);
        if (c2 == 0) {
            g_xs_cmask[(((size_t)(t * BB + b)) * NN + nblk * 32 + n2) * 16 + cblk] = cword;
        }
        __syncthreads();
    }
}

// ---------------- K1b: decode masks into ascending active lists ----------
__global__ __launch_bounds__(256) void list_kernel() {
    int lane = threadIdx.x & 31;
    int col = blockIdx.x * 8 + (threadIdx.x >> 5);   // 0..65535
    unsigned m = (lane < 16) ? g_xs_cmask[(size_t)col * 16 + lane] : 0u;
    int cnt = __popc(m);
    int incl = cnt;
#pragma unroll
    for (int d = 1; d < 32; d <<= 1) {
        int v2 = __shfl_up_sync(0xffffffffu, incl, d);
        if (lane >= d) incl += v2;
    }
    int total = __shfl_sync(0xffffffffu, incl, 31);
    int off = incl - cnt;
    unsigned short* L = g_listc + (size_t)col * 128;
    if (lane == 0) g_cntc[col] = total;
    int base = lane * 32;
    while (m) {
        int cb = __ffs(m) - 1;
        if (off < 128) L[off] = (unsigned short)(base + cb);
        off++;
        m &= m - 1;
    }
}

// ---------------- gather building blocks (strictly ascending order) ------
__device__ __forceinline__ void gstep4(const float2* __restrict__ swp,
                                       const unsigned short* __restrict__ L, int i,
                                       int lane, float& a0, float& a1) {
    uint2 e = *(const uint2*)(L + i);
    int c0 = (int)(e.x & 0xffffu), c1 = (int)(e.x >> 16);
    int c2 = (int)(e.y & 0xffffu), c3 = (int)(e.y >> 16);
    float2 w0 = swp[c0 * 32 + lane];
    float2 w1 = swp[c1 * 32 + lane];
    float2 w2 = swp[c2 * 32 + lane];
    float2 w3 = swp[c3 * 32 + lane];
    a0 += w0.x; a1 += w0.y;
    a0 += w1.x; a1 += w1.y;
    a0 += w2.x; a1 += w2.y;
    a0 += w3.x; a1 += w3.y;
}
__device__ __forceinline__ void gfinish(const float2* __restrict__ swp,
                                        const unsigned short* __restrict__ L,
                                        int i, int cnt, int lane, float& a0, float& a1) {
    for (; i + 4 <= cnt; i += 4) gstep4(swp, L, i, lane, a0, a1);
    for (; i < cnt; i++) {
        float2 w = swp[(int)L[i] * 32 + lane];
        a0 += w.x; a1 += w.y;
    }
}
// overflow-safe single-column accumulate (a0/a1 already initialized)
__device__ __forceinline__ void gov(const float2* __restrict__ swp, int col, int cnt,
                                    const unsigned short* __restrict__ L, int lane,
                                    float& a0, float& a1) {
    if (cnt <= LCAP) { gfinish(swp, L, 0, cnt, lane, a0, a1); return; }
    for (int w = 0; w < 16; w++) {
        unsigned m = g_xs_cmask[(size_t)col * 16 + w];
        int base = w * 32;
        while (m) {
            int c = base + __ffs(m) - 1;
            m &= m - 1;
            float2 ww = swp[c * 32 + lane];
            a0 += ww.x; a1 += ww.y;
        }
    }
}
// quad-column lockstep gather: 4-wide to min4 (unpredicated), then pairwise,
// then scalar tails. Per-column accumulation order stays bias + ascending-c.
__device__ __forceinline__ void gather4L(const float2* __restrict__ swp,
                                         const unsigned short* __restrict__ slist,
                                         const int* __restrict__ scnt,
                                         int cl, int col, int lane,
                                         float b0, float b1,
                                         float (&a0)[4], float (&a1)[4]) {
    int c0 = scnt[cl], c1 = scnt[cl + 1], c2 = scnt[cl + 2], c3 = scnt[cl + 3];
    const unsigned short* L0 = slist + (cl) * LCAP;
    const unsigned short* L1 = slist + (cl + 1) * LCAP;
    const unsigned short* L2 = slist + (cl + 2) * LCAP;
    const unsigned short* L3 = slist + (cl + 3) * LCAP;
    a0[0] = b0; a1[0] = b1; a0[1] = b0; a1[1] = b1;
    a0[2] = b0; a1[2] = b1; a0[3] = b0; a1[3] = b1;
    if ((c0 | c1 | c2 | c3) <= LCAP) {
        int m01 = min(c0, c1), m23 = min(c2, c3);
        int m4 = min(m01, m23);
        int i = 0;
        for (; i + 4 <= m4; i += 4) {
            gstep4(swp, L0, i, lane, a0[0], a1[0]);
            gstep4(swp, L1, i, lane, a0[1], a1[1]);
            gstep4(swp, L2, i, lane, a0[2], a1[2]);
            gstep4(swp, L3, i, lane, a0[3], a1[3]);
        }
        int i01 = i;
        for (; i01 + 4 <= m01; i01 += 4) {
            gstep4(swp, L0, i01, lane, a0[0], a1[0]);
            gstep4(swp, L1, i01, lane, a0[1], a1[1]);
        }
        gfinish(swp, L0, i01, c0, lane, a0[0], a1[0]);
        gfinish(swp, L1, i01, c1, lane, a0[1], a1[1]);
        int i23 = i;
        for (; i23 + 4 <= m23; i23 += 4) {
            gstep4(swp, L2, i23, lane, a0[2], a1[2]);
            gstep4(swp, L3, i23, lane, a0[3], a1[3]);
        }
        gfinish(swp, L2, i23, c2, lane, a0[2], a1[2]);
        gfinish(swp, L3, i23, c3, lane, a0[3], a1[3]);
    } else {
        gov(swp, col, c0, L0, lane, a0[0], a1[0]);
        gov(swp, col + 1, c1, L1, lane, a0[1], a1[1]);
        gov(swp, col + 2, c2, L2, lane, a0[2], a1[2]);
        gov(swp, col + 3, c3, L3, lane, a0[3], a1[3]);
    }
}

// cooperative staging of weights + lists + counts for the CTA's 512 columns
__device__ __forceinline__ void stage_qk(char* smem_raw, const float* __restrict__ Wsrc,
                                         int pb, int tid) {
    float4* dstw = (float4*)smem_raw;
    const float4* srcw = (const float4*)Wsrc;
    for (int e = tid; e < 8192; e += 1024) dstw[e] = srcw[e];

    unsigned* slist32 = (unsigned*)(smem_raw + SM_W_BYTES);
    int* scnt = (int*)(smem_raw + SM_W_BYTES + SM_L_BYTES);
    if (tid < 512) {
        int t = tid >> 7, i = tid & 127;
        scnt[tid] = g_cntc[t * (BB * NN) + pb * 128 + i];
    }
#pragma unroll
    for (int r = 0; r < 12; r++) {
        int e = r * 1024 + tid;
        int cl = e / 24;
        int w = e - cl * 24;
        int t = cl >> 7, i = cl & 127;
        int col = t * (BB * NN) + pb * 128 + i;
        slist32[cl * 24 + w] = ((const unsigned*)(g_listc + (size_t)col * 128))[w];
    }
}

// ---------------- K2a: q path — gather + LIF(q) + qh + attn LIF ----------
// grid = 8 heads x 128 pair-blocks; block = 1024 threads = 32 warps;
// each warp owns the head's 64 channels and its 4 pairs, all interleaved.
__global__ __launch_bounds__(1024) void q_kernel(float* __restrict__ out_attn) {
    extern __shared__ char smem_raw[];
    int tid = threadIdx.x, lane = tid & 31, warp = tid >> 5;
    int h = blockIdx.x >> 7;
    int pb = blockIdx.x & 127;

    stage_qk(smem_raw, g_Wq2 + (size_t)h * 32768, pb, tid);
    __syncthreads();

    const float2* swp = (const float2*)smem_raw;
    const unsigned short* slist = (const unsigned short*)(smem_raw + SM_W_BYTES);
    const int* scnt = (const int*)(smem_raw + SM_W_BYTES + SM_L_BYTES);

    float bias0 = g_bqk[64 * h + lane];
    float bias1 = g_bqk[64 * h + 32 + lane];

    int pl = warp * 4;                 // first local pair of this warp
    int pg = pb * 128 + pl;            // global pair (b*1024+n)
    float v0[4] = {0.f, 0.f, 0.f, 0.f};
    float v1[4] = {0.f, 0.f, 0.f, 0.f};
    float va[4] = {0.f, 0.f, 0.f, 0.f};

#pragma unroll
    for (int t = 0; t < TT; t++) {
        int cl = t * 128 + pl;
        int col = t * (BB * NN) + pg;
        float a0[4], a1[4];
        gather4L(swp, slist, scnt, cl, col, lane, bias0, bias1, a0, a1);
        unsigned sa4 = 0;
#pragma unroll
        for (int j = 0; j < 4; j++) {
            v0[j] = v0[j] + (a0[j] - v0[j]) * 0.5f;
            bool s0 = (v0[j] >= 1.0f); if (s0) v0[j] = 0.f;
            v1[j] = v1[j] + (a1[j] - v1[j]) * 0.5f;
            bool s1 = (v1[j] >= 1.0f); if (s1) v1[j] = 0.f;
            unsigned B0 = __ballot_sync(0xffffffffu, s0);
            unsigned B1 = __ballot_sync(0xffffffffu, s1);
            float qh = (float)(__popc(B0) + __popc(B1));
            va[j] = va[j] + (qh - va[j]) * 0.5f;
            bool sa = (va[j] >= 0.5f); if (sa) va[j] = 0.f;
            if (sa) sa4 |= 1u << j;
        }
        if (lane == 0) {
#pragma unroll
            for (int j = 0; j < 4; j++) {
                int b = (pg + j) >> 10, n = (pg + j) & 1023;
                bool sa = (sa4 >> j) & 1u;
                out_attn[(((size_t)(t * BB + b)) * NHEADS + h) * NN + n] = sa ? 1.f : 0.f;
                g_attn_b[((size_t)(h * TT + t)) * (BB * NN) + pg + j] = sa ? 1 : 0;
            }
        }
    }
}

// ---------------- K2b: k path — gather + LIF(k) + attn-gate -> y mask ----
__global__ __launch_bounds__(1024) void k_kernel() {
    extern __shared__ char smem_raw[];
    int tid = threadIdx.x, lane = tid & 31, warp = tid >> 5;
    int h = blockIdx.x >> 7;
    int pb = blockIdx.x & 127;

    stage_qk(smem_raw, g_Wk2 + (size_t)h * 32768, pb, tid);
    __syncthreads();

    const float2* swp = (const float2*)smem_raw;
    const unsigned short* slist = (const unsigned short*)(smem_raw + SM_W_BYTES);
    const int* scnt = (const int*)(smem_raw + SM_W_BYTES + SM_L_BYTES);

    float bias0 = g_bqk[512 + 64 * h + lane];
    float bias1 = g_bqk[512 + 64 * h + 32 + lane];

    int pl = warp * 4;
    int pg = pb * 128 + pl;
    float v0[4] = {0.f, 0.f, 0.f, 0.f};
    float v1[4] = {0.f, 0.f, 0.f, 0.f};

#pragma unroll
    for (int t = 0; t < TT; t++) {
        int cl = t * 128 + pl;
        int col = t * (BB * NN) + pg;
        float a0[4], a1[4];
        gather4L(swp, slist, scnt, cl, col, lane, bias0, bias1, a0, a1);
        unsigned B0s[4], B1s[4];
#pragma unroll
        for (int j = 0; j < 4; j++) {
            v0[j] = v0[j] + (a0[j] - v0[j]) * 0.5f;
            bool s0 = (v0[j] >= 1.0f); if (s0) v0[j] = 0.f;
            v1[j] = v1[j] + (a1[j] - v1[j]) * 0.5f;
            bool s1 = (v1[j] >= 1.0f); if (s1) v1[j] = 0.f;
            B0s[j] = __ballot_sync(0xffffffffu, s0);
            B1s[j] = __ballot_sync(0xffffffffu, s1);
        }
        if (lane == 0) {
#pragma unroll
            for (int j = 0; j < 4; j++) {
                unsigned a8 = g_attn_b[((size_t)(h * TT + t)) * (BB * NN) + pg + j];
                unsigned B0 = a8 ? B0s[j] : 0u;
                unsigned B1 = a8 ? B1s[j] : 0u;
                *(uint2*)&g_y_cmask[(size_t)(col + j) * 16 + 2 * h] = make_uint2(B0, B1);
            }
        }
    }
}

// ---------------- K3: proj GEMM — warp-per-column, high-MLP gather -------
__global__ __launch_bounds__(512) void proj_kernel(float* __restrict__ out) {
    int tid = threadIdx.x;
    int lane = tid & 31, warp = tid >> 5;
    int bid = blockIdx.x;
    int ng = bid & 63;
    int b = (bid >> 6) & 15;
    int t = bid >> 10;
    int n0 = ng * 16;

    __shared__ float stage[512 * 17];

    int n = n0 + warp;
    size_t colbase = (((size_t)(t * BB + b)) * NN + n) * 16;
    unsigned mword = (lane < 16) ? g_y_cmask[colbase + lane] : 0u;

    float acc[16];
#pragma unroll
    for (int m = 0; m < 16; m++) acc[m] = g_bp[m * 32 + lane];

#pragma unroll
    for (int w16 = 0; w16 < 16; w16++) {
        unsigned m = __shfl_sync(0xffffffffu, mword, w16);
        int base = w16 * 32;
        while (m) {
            int c = base + __ffs(m) - 1;
            m &= m - 1;
            const float* row = g_Wp + c * CC;
#pragma unroll
            for (int mm = 0; mm < 16; mm++) acc[mm] += row[mm * 32 + lane];
        }
    }

#pragma unroll
    for (int mm = 0; mm < 16; mm++) stage[(mm * 32 + lane) * 17 + warp] = acc[mm];
    __syncthreads();

    size_t obase = ((size_t)(t * BB + b)) * CC * NN + n0;
#pragma unroll
    for (int r = 0; r < 16; r++) {
        int idx = r * 512 + tid;
        int d = idx >> 4, jj = idx & 15;
        out[obase + (size_t)d * NN + jj] = stage[d * 17 + jj];
    }
}

// ---------------- launch ----------------
extern "C" void kernel_launch(void* const* d_in, const int* in_sizes, int n_in,
                              void* d_out, int out_size) {
    const float* x      = (const float*)d_in[0];
    const float* q_w    = (const float*)d_in[1];
    const float* q_g    = (const float*)d_in[2];
    const float* q_b    = (const float*)d_in[3];
    const float* q_m    = (const float*)d_in[4];
    const float* q_v    = (const float*)d_in[5];
    const float* k_w    = (const float*)d_in[6];
    const float* k_g    = (const float*)d_in[7];
    const float* k_b    = (const float*)d_in[8];
    const float* k_m    = (const float*)d_in[9];
    const float* k_v    = (const float*)d_in[10];
    const float* p_w    = (const float*)d_in[11];
    const float* p_bias = (const float*)d_in[12];
    const float* p_g    = (const float*)d_in[13];
    const float* p_b    = (const float*)d_in[14];
    const float* p_m    = (const float*)d_in[15];
    const float* p_v    = (const float*)d_in[16];

    float* out = (float*)d_out;
    const size_t Y_ELEMS = (size_t)TT * BB * CC * NN;
    const size_t A_ELEMS = (size_t)TT * BB * NHEADS * NN;

    float* attn_ptr;
    if ((size_t)out_size >= Y_ELEMS + A_ELEMS) {
        attn_ptr = out + Y_ELEMS;
    } else {
        void* p = nullptr;
        cudaGetSymbolAddress(&p, g_attn_fallback);
        attn_ptr = (float*)p;
    }

    cudaFuncSetAttribute(q_kernel, cudaFuncAttributeMaxDynamicSharedMemorySize, SMEM_QK_SZ);
    cudaFuncSetAttribute(k_kernel, cudaFuncAttributeMaxDynamicSharedMemorySize, SMEM_QK_SZ);

    prep_kernel<<<512, 512>>>(q_g, q_b, q_m, q_v, k_g, k_b, k_m, k_v,
                              p_w, p_bias, p_g, p_b, p_m, p_v);
    prep_w2_kernel<<<512, 512>>>(q_w, q_g, q_v, k_w, k_g, k_v);
    lif_x_kernel<<<16 * 16 * 32, 1024>>>(x);
    list_kernel<<<8192, 256>>>();
    q_kernel<<<NHEADS * 128, 1024, SMEM_QK_SZ>>>(attn_ptr);
    k_kernel<<<NHEADS * 128, 1024, SMEM_QK_SZ>>>();
    proj_kernel<<<TT * BB * 64, 512>>>(out);
}

// round 15
// speedup vs baseline: 1.0658x; 1.0658x over previous
#include <cuda_runtime.h>
#include <math.h>
#include <stdint.h>

#define TT 4
#define BB 16
#define CC 512
#define NN 1024
#define NHEADS 8
#define LCAP 48   // staged list cap (mean ~18, binomial std ~4.2 -> 7 sigma)

// ---------------- device scratch (no allocations allowed) ----------------
__device__ float g_Wp[CC * CC];            // [c][d], BN-folded proj
__device__ float g_bqk[1024];              // [0..511]=q bias, [512..1023]=k bias
__device__ float g_bp[CC];
// per-head weight slices, layout [h][c][e] with e=2*l+j <-> channel 64h + l + 32j
__device__ float g_Wq2[NHEADS * CC * 64];  // 1 MB
__device__ float g_Wk2[NHEADS * CC * 64];  // 1 MB
__device__ unsigned g_xs_cmask[TT * BB * NN * 16];
__device__ unsigned g_y_cmask[TT * BB * NN * 16];
// per-column active-channel list: entries from index 0 (4B-aligned), count separate
__device__ unsigned short g_listc[TT * BB * NN * 128];  // 16 MB
__device__ int g_cntc[TT * BB * NN];                    // 256 KB
__device__ float g_attn_fallback[TT * BB * NHEADS * NN];

// smem layout for fused qk kernel
#define SM_W_BYTES   131072
#define SM_L_BYTES   (512 * LCAP * 2)          // 49152
#define SM_C_BYTES   2048
#define SMEM_QK_SZ   (SM_W_BYTES + SM_L_BYTES + SM_C_BYTES)   // 182272

// ---------------- K0a: fold BN into proj weights + biases ----------------
__global__ void prep_kernel(const float* __restrict__ qg, const float* __restrict__ qb,
                            const float* __restrict__ qm, const float* __restrict__ qv,
                            const float* __restrict__ kg, const float* __restrict__ kb,
                            const float* __restrict__ km, const float* __restrict__ kv,
                            const float* __restrict__ pw, const float* __restrict__ pbias,
                            const float* __restrict__ pg, const float* __restrict__ pb,
                            const float* __restrict__ pm, const float* __restrict__ pv) {
    int idx = blockIdx.x * blockDim.x + threadIdx.x;  // 512*512
    int d = idx & 511;
    int c = idx >> 9;
    float invp = (float)((double)pg[d] / sqrt((double)pv[d] + 1e-5));
    g_Wp[c * CC + d] = pw[d * CC + c] * invp;
    if (c == 0) {
        float invq = (float)((double)qg[d] / sqrt((double)qv[d] + 1e-5));
        float invk = (float)((double)kg[d] / sqrt((double)kv[d] + 1e-5));
        g_bqk[d]       = qb[d] - qm[d] * invq;
        g_bqk[512 + d] = kb[d] - km[d] * invk;
        g_bp[d]        = pbias[d] * invp + pb[d] - pm[d] * invp;
    }
}

// ---------------- K0b: per-head q/k weight slices, BN-folded -------------
__global__ __launch_bounds__(512) void prep_w2_kernel(
        const float* __restrict__ qw, const float* __restrict__ qg, const float* __restrict__ qv,
        const float* __restrict__ kw, const float* __restrict__ kg, const float* __restrict__ kv) {
    int idx = blockIdx.x * blockDim.x + threadIdx.x;  // 262144
    int e = idx & 63;
    int c = (idx >> 6) & 511;
    int h = idx >> 15;
    int d = 64 * h + (e >> 1) + 32 * (e & 1);
    float invq = (float)((double)qg[d] / sqrt((double)qv[d] + 1e-5));
    float invk = (float)((double)kg[d] / sqrt((double)kv[d] + 1e-5));
    g_Wq2[idx] = qw[d * CC + c] * invq;
    g_Wk2[idx] = kw[d * CC + c] * invk;
}

// ---------------- K1: LIF over x, pack channel bitmasks ----------------
__global__ __launch_bounds__(1024) void lif_x_kernel(const float* __restrict__ x) {
    int tid = threadIdx.x;
    int bid = blockIdx.x;
    int nblk = bid & 31;
    int cblk = (bid >> 5) & 15;
    int b = bid >> 9;
    int c_l = tid >> 5, n_l = tid & 31;
    int c = cblk * 32 + c_l;
    int n = nblk * 32 + n_l;
    __shared__ unsigned sw[32];
    const float* xp = x + ((size_t)b * CC + c) * NN + n;
    float xv[TT];
#pragma unroll
    for (int t = 0; t < TT; t++) xv[t] = xp[(size_t)t * BB * CC * NN];
    float v = 0.f;
#pragma unroll
    for (int t = 0; t < TT; t++) {
        v = v + (xv[t] - v) * 0.5f;
        bool s = (v >= 1.0f);
        if (s) v = 0.f;
        unsigned bm = __ballot_sync(0xffffffffu, s);
        if (n_l == 0) sw[c_l] = bm;
        __syncthreads();
        int n2 = tid >> 5, c2 = tid & 31;
        bool bit = (sw[c2] >> n2) & 1u;
        unsigned cword = __ballot_sync(0xffffffffu, bit);
        if (c2 == 0) {
            g_xs_cmask[(((size_t)(t * BB + b)) * NN + nblk * 32 + n2) * 16 + cblk] = cword;
        }
        __syncthreads();
    }
}

// ---------------- K1b: decode masks into ascending active lists ----------
__global__ __launch_bounds__(256) void list_kernel() {
    int lane = threadIdx.x & 31;
    int col = blockIdx.x * 8 + (threadIdx.x >> 5);   // 0..65535
    unsigned m = (lane < 16) ? g_xs_cmask[(size_t)col * 16 + lane] : 0u;
    int cnt = __popc(m);
    int incl = cnt;
#pragma unroll
    for (int d = 1; d < 32; d <<= 1) {
        int v2 = __shfl_up_sync(0xffffffffu, incl, d);
        if (lane >= d) incl += v2;
    }
    int total = __shfl_sync(0xffffffffu, incl, 31);
    int off = incl - cnt;
    unsigned short* L = g_listc + (size_t)col * 128;
    if (lane == 0) g_cntc[col] = total;
    int base = lane * 32;
    while (m) {
        int cb = __ffs(m) - 1;
        if (off < 128) L[off] = (unsigned short)(base + cb);
        off++;
        m &= m - 1;
    }
}

// ---------------- gather building blocks (strictly ascending order) ------
__device__ __forceinline__ void gstep4(const float2* __restrict__ swp,
                                       const unsigned short* __restrict__ L, int i,
                                       int lane, float& a0, float& a1) {
    uint2 e = *(const uint2*)(L + i);
    int c0 = (int)(e.x & 0xffffu), c1 = (int)(e.x >> 16);
    int c2 = (int)(e.y & 0xffffu), c3 = (int)(e.y >> 16);
    float2 w0 = swp[c0 * 32 + lane];
    float2 w1 = swp[c1 * 32 + lane];
    float2 w2 = swp[c2 * 32 + lane];
    float2 w3 = swp[c3 * 32 + lane];
    a0 += w0.x; a1 += w0.y;
    a0 += w1.x; a1 += w1.y;
    a0 += w2.x; a1 += w2.y;
    a0 += w3.x; a1 += w3.y;
}
__device__ __forceinline__ void gfinish(const float2* __restrict__ swp,
                                        const unsigned short* __restrict__ L,
                                        int i, int cnt, int lane, float& a0, float& a1) {
    for (; i + 4 <= cnt; i += 4) gstep4(swp, L, i, lane, a0, a1);
    for (; i < cnt; i++) {
        float2 w = swp[(int)L[i] * 32 + lane];
        a0 += w.x; a1 += w.y;
    }
}
// overflow-safe single-column accumulate (a0/a1 already initialized)
__device__ __forceinline__ void gov(const float2* __restrict__ swp, int col, int cnt,
                                    const unsigned short* __restrict__ L, int lane,
                                    float& a0, float& a1) {
    if (cnt <= LCAP) { gfinish(swp, L, 0, cnt, lane, a0, a1); return; }
    for (int w = 0; w < 16; w++) {
        unsigned m = g_xs_cmask[(size_t)col * 16 + w];
        int base = w * 32;
        while (m) {
            int c = base + __ffs(m) - 1;
            m &= m - 1;
            float2 ww = swp[c * 32 + lane];
            a0 += ww.x; a1 += ww.y;
        }
    }
}
// dual-column interleaved gather: lockstep to min(cA,cB) unpredicated, then tails
__device__ __forceinline__ void gather2(const float2* __restrict__ swp,
                                        const unsigned short* __restrict__ slist,
                                        const int* __restrict__ scnt,
                                        int clA, int clB, int colA, int colB, int lane,
                                        float b0, float b1,
                                        float& a0A, float& a1A, float& a0B, float& a1B) {
    int cA = scnt[clA], cB = scnt[clB];
    const unsigned short* LA = slist + clA * LCAP;
    const unsigned short* LB = slist + clB * LCAP;
    a0A = b0; a1A = b1; a0B = b0; a1B = b1;
    if (cA <= LCAP && cB <= LCAP) {
        int cmin = min(cA, cB);
        int i = 0;
        for (; i + 4 <= cmin; i += 4) {
            gstep4(swp, LA, i, lane, a0A, a1A);
            gstep4(swp, LB, i, lane, a0B, a1B);
        }
        gfinish(swp, LA, i, cA, lane, a0A, a1A);
        gfinish(swp, LB, i, cB, lane, a0B, a1B);
    } else {
        gov(swp, colA, cA, LA, lane, a0A, a1A);
        gov(swp, colB, cB, LB, lane, a0B, a1B);
    }
}

// ---------------- K2: fused q+k — two phases over the same staged lists --
// grid = 8 heads x 128 pair-blocks; block = 1024 threads = 32 warps;
// each warp owns the head's 64 channels; 2x2 pairs, 2 interleaved.
__global__ __launch_bounds__(1024) void qk_kernel(float* __restrict__ out_attn) {
    extern __shared__ char smem_raw[];
    int tid = threadIdx.x, lane = tid & 31, warp = tid >> 5;
    int h = blockIdx.x >> 7;
    int pb = blockIdx.x & 127;

    // ---- stage lists + counts (once) and q weights ----
    {
        float4* dstw = (float4*)smem_raw;
        const float4* srcw = (const float4*)(g_Wq2 + (size_t)h * 32768);
        for (int e = tid; e < 8192; e += 1024) dstw[e] = srcw[e];
        unsigned* slist32 = (unsigned*)(smem_raw + SM_W_BYTES);
        int* scnt_w = (int*)(smem_raw + SM_W_BYTES + SM_L_BYTES);
        if (tid < 512) {
            int t = tid >> 7, i = tid & 127;
            scnt_w[tid] = g_cntc[t * (BB * NN) + pb * 128 + i];
        }
#pragma unroll
        for (int r = 0; r < 12; r++) {
            int e = r * 1024 + tid;
            int cl = e / 24;
            int w = e - cl * 24;
            int t = cl >> 7, i = cl & 127;
            int col = t * (BB * NN) + pb * 128 + i;
            slist32[cl * 24 + w] = ((const unsigned*)(g_listc + (size_t)col * 128))[w];
        }
    }
    __syncthreads();

    const float2* swp = (const float2*)smem_raw;
    const unsigned short* slist = (const unsigned short*)(smem_raw + SM_W_BYTES);
    const int* scnt = (const int*)(smem_raw + SM_W_BYTES + SM_L_BYTES);

    // ================= Phase A: q + qh + attn-LIF =================
    unsigned amask = 0;   // warp-uniform attn bits: bit = pl*4 + t (pl = local pair 0..3)
    {
        float bias0 = g_bqk[64 * h + lane];
        float bias1 = g_bqk[64 * h + 32 + lane];
        for (int pp = 0; pp < 4; pp += 2) {
            int plA = warp * 4 + pp;
            int pgA = pb * 128 + plA;
            int bA = pgA >> 10, nA = pgA & 1023;
            int bB = (pgA + 1) >> 10, nB = (pgA + 1) & 1023;
            float v0A = 0.f, v1A = 0.f, vaA = 0.f;
            float v0B = 0.f, v1B = 0.f, vaB = 0.f;
#pragma unroll
            for (int t = 0; t < TT; t++) {
                int clA = t * 128 + plA;
                int colA = t * (BB * NN) + pgA;
                float a0A, a1A, a0B, a1B;
                gather2(swp, slist, scnt, clA, clA + 1, colA, colA + 1, lane,
                        bias0, bias1, a0A, a1A, a0B, a1B);
                v0A = v0A + (a0A - v0A) * 0.5f;
                bool s0A = (v0A >= 1.0f); if (s0A) v0A = 0.f;
                v1A = v1A + (a1A - v1A) * 0.5f;
                bool s1A = (v1A >= 1.0f); if (s1A) v1A = 0.f;
                v0B = v0B + (a0B - v0B) * 0.5f;
                bool s0B = (v0B >= 1.0f); if (s0B) v0B = 0.f;
                v1B = v1B + (a1B - v1B) * 0.5f;
                bool s1B = (v1B >= 1.0f); if (s1B) v1B = 0.f;
                unsigned B0A = __ballot_sync(0xffffffffu, s0A);
                unsigned B1A = __ballot_sync(0xffffffffu, s1A);
                unsigned B0B = __ballot_sync(0xffffffffu, s0B);
                unsigned B1B = __ballot_sync(0xffffffffu, s1B);
                float qhA = (float)(__popc(B0A) + __popc(B1A));
                float qhB = (float)(__popc(B0B) + __popc(B1B));
                vaA = vaA + (qhA - vaA) * 0.5f;
                bool saA = (vaA >= 0.5f); if (saA) vaA = 0.f;
                vaB = vaB + (qhB - vaB) * 0.5f;
                bool saB = (vaB >= 0.5f); if (saB) vaB = 0.f;
                if (saA) amask |= 1u << ((pp) * 4 + t);
                if (saB) amask |= 1u << ((pp + 1) * 4 + t);
                if (lane == 0) {
                    out_attn[(((size_t)(t * BB + bA)) * NHEADS + h) * NN + nA] = saA ? 1.f : 0.f;
                    out_attn[(((size_t)(t * BB + bB)) * NHEADS + h) * NN + nB] = saB ? 1.f : 0.f;
                }
            }
        }
    }

    // ---- swap weights: Wq -> Wk (lists/counts stay) ----
    __syncthreads();
    {
        float4* dstw = (float4*)smem_raw;
        const float4* srcw = (const float4*)(g_Wk2 + (size_t)h * 32768);
        for (int e = tid; e < 8192; e += 1024) dstw[e] = srcw[e];
    }
    __syncthreads();

    // ================= Phase B: k + attn-gate -> y mask =================
    {
        float bias0 = g_bqk[512 + 64 * h + lane];
        float bias1 = g_bqk[512 + 64 * h + 32 + lane];
        for (int pp = 0; pp < 4; pp += 2) {
            int plA = warp * 4 + pp;
            int pgA = pb * 128 + plA;
            float v0A = 0.f, v1A = 0.f, v0B = 0.f, v1B = 0.f;
#pragma unroll
            for (int t = 0; t < TT; t++) {
                int clA = t * 128 + plA;
                int colA = t * (BB * NN) + pgA;
                float a0A, a1A, a0B, a1B;
                gather2(swp, slist, scnt, clA, clA + 1, colA, colA + 1, lane,
                        bias0, bias1, a0A, a1A, a0B, a1B);
                v0A = v0A + (a0A - v0A) * 0.5f;
                bool s0A = (v0A >= 1.0f); if (s0A) v0A = 0.f;
                v1A = v1A + (a1A - v1A) * 0.5f;
                bool s1A = (v1A >= 1.0f); if (s1A) v1A = 0.f;
                v0B = v0B + (a0B - v0B) * 0.5f;
                bool s0B = (v0B >= 1.0f); if (s0B) v0B = 0.f;
                v1B = v1B + (a1B - v1B) * 0.5f;
                bool s1B = (v1B >= 1.0f); if (s1B) v1B = 0.f;
                unsigned B0A = __ballot_sync(0xffffffffu, s0A);
                unsigned B1A = __ballot_sync(0xffffffffu, s1A);
                unsigned B0B = __ballot_sync(0xffffffffu, s0B);
                unsigned B1B = __ballot_sync(0xffffffffu, s1B);
                bool gA = (amask >> ((pp) * 4 + t)) & 1u;
                bool gB = (amask >> ((pp + 1) * 4 + t)) & 1u;
                if (!gA) { B0A = 0u; B1A = 0u; }
                if (!gB) { B0B = 0u; B1B = 0u; }
                if (lane == 0) {
                    *(uint2*)&g_y_cmask[(size_t)colA * 16 + 2 * h] = make_uint2(B0A, B1A);
                    *(uint2*)&g_y_cmask[(size_t)(colA + 1) * 16 + 2 * h] = make_uint2(B0B, B1B);
                }
            }
        }
    }
}

// ---------------- K3: proj GEMM — warp-per-column, high-MLP gather -------
__global__ __launch_bounds__(512) void proj_kernel(float* __restrict__ out) {
    int tid = threadIdx.x;
    int lane = tid & 31, warp = tid >> 5;
    int bid = blockIdx.x;
    int ng = bid & 63;
    int b = (bid >> 6) & 15;
    int t = bid >> 10;
    int n0 = ng * 16;

    __shared__ float stage[512 * 17];

    int n = n0 + warp;
    size_t colbase = (((size_t)(t * BB + b)) * NN + n) * 16;
    unsigned mword = (lane < 16) ? g_y_cmask[colbase + lane] : 0u;

    float acc[16];
#pragma unroll
    for (int m = 0; m < 16; m++) acc[m] = g_bp[m * 32 + lane];

#pragma unroll
    for (int w16 = 0; w16 < 16; w16++) {
        unsigned m = __shfl_sync(0xffffffffu, mword, w16);
        int base = w16 * 32;
        while (m) {
            int c = base + __ffs(m) - 1;
            m &= m - 1;
            const float* row = g_Wp + c * CC;
#pragma unroll
            for (int mm = 0; mm < 16; mm++) acc[mm] += row[mm * 32 + lane];
        }
    }

#pragma unroll
    for (int mm = 0; mm < 16; mm++) stage[(mm * 32 + lane) * 17 + warp] = acc[mm];
    __syncthreads();

    size_t obase = ((size_t)(t * BB + b)) * CC * NN + n0;
#pragma unroll
    for (int r = 0; r < 16; r++) {
        int idx = r * 512 + tid;
        int d = idx >> 4, jj = idx & 15;
        out[obase + (size_t)d * NN + jj] = stage[d * 17 + jj];
    }
}

// ---------------- launch ----------------
extern "C" void kernel_launch(void* const* d_in, const int* in_sizes, int n_in,
                              void* d_out, int out_size) {
    const float* x      = (const float*)d_in[0];
    const float* q_w    = (const float*)d_in[1];
    const float* q_g    = (const float*)d_in[2];
    const float* q_b    = (const float*)d_in[3];
    const float* q_m    = (const float*)d_in[4];
    const float* q_v    = (const float*)d_in[5];
    const float* k_w    = (const float*)d_in[6];
    const float* k_g    = (const float*)d_in[7];
    const float* k_b    = (const float*)d_in[8];
    const float* k_m    = (const float*)d_in[9];
    const float* k_v    = (const float*)d_in[10];
    const float* p_w    = (const float*)d_in[11];
    const float* p_bias = (const float*)d_in[12];
    const float* p_g    = (const float*)d_in[13];
    const float* p_b    = (const float*)d_in[14];
    const float* p_m    = (const float*)d_in[15];
    const float* p_v    = (const float*)d_in[16];

    float* out = (float*)d_out;
    const size_t Y_ELEMS = (size_t)TT * BB * CC * NN;
    const size_t A_ELEMS = (size_t)TT * BB * NHEADS * NN;

    float* attn_ptr;
    if ((size_t)out_size >= Y_ELEMS + A_ELEMS) {
        attn_ptr = out + Y_ELEMS;
    } else {
        void* p = nullptr;
        cudaGetSymbolAddress(&p, g_attn_fallback);
        attn_ptr = (float*)p;
    }

    cudaFuncSetAttribute(qk_kernel, cudaFuncAttributeMaxDynamicSharedMemorySize, SMEM_QK_SZ);

    prep_kernel<<<512, 512>>>(q_g, q_b, q_m, q_v, k_g, k_b, k_m, k_v,
                              p_w, p_bias, p_g, p_b, p_m, p_v);
    prep_w2_kernel<<<512, 512>>>(q_w, q_g, q_v, k_w, k_g, k_v);
    lif_x_kernel<<<16 * 16 * 32, 1024>>>(x);
    list_kernel<<<8192, 256>>>();
    qk_kernel<<<NHEADS * 128, 1024, SMEM_QK_SZ>>>(attn_ptr);
    proj_kernel<<<TT * BB * 64, 512>>>(out);
}

// round 16
// speedup vs baseline: 1.1438x; 1.0732x over previous
#include <cuda_runtime.h>
#include <math.h>
#include <stdint.h>

#define TT 4
#define BB 16
#define CC 512
#define NN 1024
#define NHEADS 8
#define LCAP 48   // staged list cap (mean ~18, binomial std ~4.2 -> 7 sigma)

// ---------------- device scratch (no allocations allowed) ----------------
__device__ float g_Wp[CC * CC];            // [c][d], BN-folded proj
__device__ float g_bqk[1024];              // [0..511]=q bias, [512..1023]=k bias
__device__ float g_bp[CC];
// per-head weight slices, layout [h][c][e] with e=2*l+j <-> channel 64h + l + 32j
__device__ float g_Wq2[NHEADS * CC * 64];  // 1 MB
__device__ float g_Wk2[NHEADS * CC * 64];  // 1 MB
__device__ unsigned g_xs_cmask[TT * BB * NN * 16];
__device__ unsigned g_y_cmask[TT * BB * NN * 16];
// per-column active-channel list: 64-ushort stride (128B rows), entries 0..LCAP-1
__device__ unsigned short g_listc[TT * BB * NN * 64];   // 8 MB
__device__ int g_cntc[TT * BB * NN];                    // 256 KB
__device__ float g_attn_fallback[TT * BB * NHEADS * NN];

// smem layout for fused qk kernel
#define SM_W_BYTES   131072
#define SM_L_BYTES   (512 * LCAP * 2)          // 49152 (96 B per column)
#define SM_C_BYTES   2048
#define SMEM_QK_SZ   (SM_W_BYTES + SM_L_BYTES + SM_C_BYTES)   // 182272

// ---------------- cp.async helpers ----------------
__device__ __forceinline__ uint32_t smem_u32(const void* p) {
    uint32_t a;
    asm("{ .reg .u64 t; cvta.to.shared.u64 t, %1; cvt.u32.u64 %0, t; }" : "=r"(a) : "l"(p));
    return a;
}
__device__ __forceinline__ void cpa16(uint32_t dst, const void* src) {
    asm volatile("cp.async.cg.shared.global [%0], [%1], 16;" :: "r"(dst), "l"(src));
}
__device__ __forceinline__ void cpa_commit() {
    asm volatile("cp.async.commit_group;" ::: "memory");
}
__device__ __forceinline__ void cpa_wait0() {
    asm volatile("cp.async.wait_group 0;" ::: "memory");
}

// ---------------- K0: fold BN into all weights + biases (merged) ---------
__global__ __launch_bounds__(512) void prep_all_kernel(
        const float* __restrict__ qw, const float* __restrict__ qg,
        const float* __restrict__ qb, const float* __restrict__ qm,
        const float* __restrict__ qv,
        const float* __restrict__ kw, const float* __restrict__ kg,
        const float* __restrict__ kb, const float* __restrict__ km,
        const float* __restrict__ kv,
        const float* __restrict__ pw, const float* __restrict__ pbias,
        const float* __restrict__ pg, const float* __restrict__ pb,
        const float* __restrict__ pm, const float* __restrict__ pv) {
    int gidx = blockIdx.x * blockDim.x + threadIdx.x;   // 0..524287
    if (gidx < 262144) {
        int idx = gidx;
        int d = idx & 511;
        int c = idx >> 9;
        float invp = (float)((double)pg[d] / sqrt((double)pv[d] + 1e-5));
        g_Wp[c * CC + d] = pw[d * CC + c] * invp;
        if (c == 0) {
            float invq = (float)((double)qg[d] / sqrt((double)qv[d] + 1e-5));
            float invk = (float)((double)kg[d] / sqrt((double)kv[d] + 1e-5));
            g_bqk[d]       = qb[d] - qm[d] * invq;
            g_bqk[512 + d] = kb[d] - km[d] * invk;
            g_bp[d]        = pbias[d] * invp + pb[d] - pm[d] * invp;
        }
    } else {
        int idx = gidx - 262144;
        int e = idx & 63;
        int c = (idx >> 6) & 511;
        int h = idx >> 15;
        int d = 64 * h + (e >> 1) + 32 * (e & 1);
        float invq = (float)((double)qg[d] / sqrt((double)qv[d] + 1e-5));
        float invk = (float)((double)kg[d] / sqrt((double)kv[d] + 1e-5));
        g_Wq2[idx] = qw[d * CC + c] * invq;
        g_Wk2[idx] = kw[d * CC + c] * invk;
    }
}

// ---------------- K1: LIF over x, pack channel bitmasks ----------------
__global__ __launch_bounds__(1024) void lif_x_kernel(const float* __restrict__ x) {
    int tid = threadIdx.x;
    int bid = blockIdx.x;
    int nblk = bid & 31;
    int cblk = (bid >> 5) & 15;
    int b = bid >> 9;
    int c_l = tid >> 5, n_l = tid & 31;
    int c = cblk * 32 + c_l;
    int n = nblk * 32 + n_l;
    __shared__ unsigned sw[32];
    const float* xp = x + ((size_t)b * CC + c) * NN + n;
    float xv[TT];
#pragma unroll
    for (int t = 0; t < TT; t++) xv[t] = xp[(size_t)t * BB * CC * NN];
    float v = 0.f;
#pragma unroll
    for (int t = 0; t < TT; t++) {
        v = v + (xv[t] - v) * 0.5f;
        bool s = (v >= 1.0f);
        if (s) v = 0.f;
        unsigned bm = __ballot_sync(0xffffffffu, s);
        if (n_l == 0) sw[c_l] = bm;
        __syncthreads();
        int n2 = tid >> 5, c2 = tid & 31;
        bool bit = (sw[c2] >> n2) & 1u;
        unsigned cword = __ballot_sync(0xffffffffu, bit);
        if (c2 == 0) {
            g_xs_cmask[(((size_t)(t * BB + b)) * NN + nblk * 32 + n2) * 16 + cblk] = cword;
        }
        __syncthreads();
    }
}

// ---------------- K1b: decode masks into ascending active lists ----------
__global__ __launch_bounds__(256) void list_kernel() {
    int lane = threadIdx.x & 31;
    int col = blockIdx.x * 8 + (threadIdx.x >> 5);   // 0..65535
    unsigned m = (lane < 16) ? g_xs_cmask[(size_t)col * 16 + lane] : 0u;
    int cnt = __popc(m);
    int incl = cnt;
#pragma unroll
    for (int d = 1; d < 32; d <<= 1) {
        int v2 = __shfl_up_sync(0xffffffffu, incl, d);
        if (lane >= d) incl += v2;
    }
    int total = __shfl_sync(0xffffffffu, incl, 31);
    int off = incl - cnt;
    unsigned short* L = g_listc + (size_t)col * 64;
    if (lane == 0) g_cntc[col] = total;
    int base = lane * 32;
    while (m) {
        int cb = __ffs(m) - 1;
        if (off < LCAP) L[off] = (unsigned short)(base + cb);
        off++;
        m &= m - 1;
    }
}

// ---------------- gather building blocks (strictly ascending order) ------
__device__ __forceinline__ void gstep4(const float2* __restrict__ swp,
                                       const unsigned short* __restrict__ L, int i,
                                       int lane, float& a0, float& a1) {
    uint2 e = *(const uint2*)(L + i);
    int c0 = (int)(e.x & 0xffffu), c1 = (int)(e.x >> 16);
    int c2 = (int)(e.y & 0xffffu), c3 = (int)(e.y >> 16);
    float2 w0 = swp[c0 * 32 + lane];
    float2 w1 = swp[c1 * 32 + lane];
    float2 w2 = swp[c2 * 32 + lane];
    float2 w3 = swp[c3 * 32 + lane];
    a0 += w0.x; a1 += w0.y;
    a0 += w1.x; a1 += w1.y;
    a0 += w2.x; a1 += w2.y;
    a0 += w3.x; a1 += w3.y;
}
__device__ __forceinline__ void gfinish(const float2* __restrict__ swp,
                                        const unsigned short* __restrict__ L,
                                        int i, int cnt, int lane, float& a0, float& a1) {
    for (; i + 4 <= cnt; i += 4) gstep4(swp, L, i, lane, a0, a1);
    for (; i < cnt; i++) {
        float2 w = swp[(int)L[i] * 32 + lane];
        a0 += w.x; a1 += w.y;
    }
}
// overflow-safe single-column accumulate (a0/a1 already initialized)
__device__ __forceinline__ void gov(const float2* __restrict__ swp, int col, int cnt,
                                    const unsigned short* __restrict__ L, int lane,
                                    float& a0, float& a1) {
    if (cnt <= LCAP) { gfinish(swp, L, 0, cnt, lane, a0, a1); return; }
    for (int w = 0; w < 16; w++) {
        unsigned m = g_xs_cmask[(size_t)col * 16 + w];
        int base = w * 32;
        while (m) {
            int c = base + __ffs(m) - 1;
            m &= m - 1;
            float2 ww = swp[c * 32 + lane];
            a0 += ww.x; a1 += ww.y;
        }
    }
}
// dual-column interleaved gather: lockstep to min(cA,cB) unpredicated, then tails
__device__ __forceinline__ void gather2(const float2* __restrict__ swp,
                                        const unsigned short* __restrict__ slist,
                                        const int* __restrict__ scnt,
                                        int clA, int clB, int colA, int colB, int lane,
                                        float b0, float b1,
                                        float& a0A, float& a1A, float& a0B, float& a1B) {
    int cA = scnt[clA], cB = scnt[clB];
    const unsigned short* LA = slist + clA * LCAP;
    const unsigned short* LB = slist + clB * LCAP;
    a0A = b0; a1A = b1; a0B = b0; a1B = b1;
    if (cA <= LCAP && cB <= LCAP) {
        int cmin = min(cA, cB);
        int i = 0;
        for (; i + 4 <= cmin; i += 4) {
            gstep4(swp, LA, i, lane, a0A, a1A);
            gstep4(swp, LB, i, lane, a0B, a1B);
        }
        gfinish(swp, LA, i, cA, lane, a0A, a1A);
        gfinish(swp, LB, i, cB, lane, a0B, a1B);
    } else {
        gov(swp, colA, cA, LA, lane, a0A, a1A);
        gov(swp, colB, cB, LB, lane, a0B, a1B);
    }
}

// ---------------- K2: fused q+k — two phases over the same staged lists --
// grid = 8 heads x 128 pair-blocks; block = 1024 threads = 32 warps;
// each warp owns the head's 64 channels; 2x2 pairs, 2 interleaved.
__global__ __launch_bounds__(1024) void qk_kernel(float* __restrict__ out_attn) {
    extern __shared__ char smem_raw[];
    int tid = threadIdx.x, lane = tid & 31, warp = tid >> 5;
    int h = blockIdx.x >> 7;
    int pb = blockIdx.x & 127;

    uint32_t sw_base = smem_u32(smem_raw);
    uint32_t sl_base = sw_base + SM_W_BYTES;
    uint32_t sc_base = sl_base + SM_L_BYTES;

    // ---- stage (cp.async): q weights + lists + counts ----
    {
        const char* srcw = (const char*)(g_Wq2 + (size_t)h * 32768);
        for (int e = tid; e < 8192; e += 1024)
            cpa16(sw_base + e * 16, srcw + e * 16);
        // lists: 512 columns x 6 x 16B (96 B per column)
        for (int e = tid; e < 3072; e += 1024) {
            int cl = e / 6;
            int w = e - cl * 6;
            int t = cl >> 7, i = cl & 127;
            int col = t * (BB * NN) + pb * 128 + i;
            cpa16(sl_base + cl * 96 + w * 16,
                  (const char*)g_listc + (size_t)col * 128 + w * 16);
        }
        // counts: 4 runs of 128 ints (512 B each)
        if (tid < 128) {
            int t = tid >> 5, w = tid & 31;
            cpa16(sc_base + t * 512 + w * 16,
                  (const char*)(g_cntc + t * (BB * NN) + pb * 128) + w * 16);
        }
        cpa_commit();
        cpa_wait0();
    }
    __syncthreads();

    const float2* swp = (const float2*)smem_raw;
    const unsigned short* slist = (const unsigned short*)(smem_raw + SM_W_BYTES);
    const int* scnt = (const int*)(smem_raw + SM_W_BYTES + SM_L_BYTES);

    // ================= Phase A: q + qh + attn-LIF =================
    unsigned amask = 0;   // warp-uniform attn bits: bit = pl*4 + t (pl = local pair 0..3)
    {
        float bias0 = g_bqk[64 * h + lane];
        float bias1 = g_bqk[64 * h + 32 + lane];
        for (int pp = 0; pp < 4; pp += 2) {
            int plA = warp * 4 + pp;
            int pgA = pb * 128 + plA;
            int bA = pgA >> 10, nA = pgA & 1023;
            int bB = (pgA + 1) >> 10, nB = (pgA + 1) & 1023;
            float v0A = 0.f, v1A = 0.f, vaA = 0.f;
            float v0B = 0.f, v1B = 0.f, vaB = 0.f;
#pragma unroll
            for (int t = 0; t < TT; t++) {
                int clA = t * 128 + plA;
                int colA = t * (BB * NN) + pgA;
                float a0A, a1A, a0B, a1B;
                gather2(swp, slist, scnt, clA, clA + 1, colA, colA + 1, lane,
                        bias0, bias1, a0A, a1A, a0B, a1B);
                v0A = v0A + (a0A - v0A) * 0.5f;
                bool s0A = (v0A >= 1.0f); if (s0A) v0A = 0.f;
                v1A = v1A + (a1A - v1A) * 0.5f;
                bool s1A = (v1A >= 1.0f); if (s1A) v1A = 0.f;
                v0B = v0B + (a0B - v0B) * 0.5f;
                bool s0B = (v0B >= 1.0f); if (s0B) v0B = 0.f;
                v1B = v1B + (a1B - v1B) * 0.5f;
                bool s1B = (v1B >= 1.0f); if (s1B) v1B = 0.f;
                unsigned B0A = __ballot_sync(0xffffffffu, s0A);
                unsigned B1A = __ballot_sync(0xffffffffu, s1A);
                unsigned B0B = __ballot_sync(0xffffffffu, s0B);
                unsigned B1B = __ballot_sync(0xffffffffu, s1B);
                float qhA = (float)(__popc(B0A) + __popc(B1A));
                float qhB = (float)(__popc(B0B) + __popc(B1B));
                vaA = vaA + (qhA - vaA) * 0.5f;
                bool saA = (vaA >= 0.5f); if (saA) vaA = 0.f;
                vaB = vaB + (qhB - vaB) * 0.5f;
                bool saB = (vaB >= 0.5f); if (saB) vaB = 0.f;
                if (saA) amask |= 1u << ((pp) * 4 + t);
                if (saB) amask |= 1u << ((pp + 1) * 4 + t);
                if (lane == 0) {
                    out_attn[(((size_t)(t * BB + bA)) * NHEADS + h) * NN + nA] = saA ? 1.f : 0.f;
                    out_attn[(((size_t)(t * BB + bB)) * NHEADS + h) * NN + nB] = saB ? 1.f : 0.f;
                }
            }
        }
    }

    // ---- swap weights: Wq -> Wk via cp.async (lists/counts stay) ----
    __syncthreads();
    {
        const char* srcw = (const char*)(g_Wk2 + (size_t)h * 32768);
        for (int e = tid; e < 8192; e += 1024)
            cpa16(sw_base + e * 16, srcw + e * 16);
        cpa_commit();
        cpa_wait0();
    }
    __syncthreads();

    // ================= Phase B: k + attn-gate -> y mask =================
    {
        float bias0 = g_bqk[512 + 64 * h + lane];
        float bias1 = g_bqk[512 + 64 * h + 32 + lane];
        for (int pp = 0; pp < 4; pp += 2) {
            int plA = warp * 4 + pp;
            int pgA = pb * 128 + plA;
            float v0A = 0.f, v1A = 0.f, v0B = 0.f, v1B = 0.f;
#pragma unroll
            for (int t = 0; t < TT; t++) {
                int clA = t * 128 + plA;
                int colA = t * (BB * NN) + pgA;
                float a0A, a1A, a0B, a1B;
                gather2(swp, slist, scnt, clA, clA + 1, colA, colA + 1, lane,
                        bias0, bias1, a0A, a1A, a0B, a1B);
                v0A = v0A + (a0A - v0A) * 0.5f;
                bool s0A = (v0A >= 1.0f); if (s0A) v0A = 0.f;
                v1A = v1A + (a1A - v1A) * 0.5f;
                bool s1A = (v1A >= 1.0f); if (s1A) v1A = 0.f;
                v0B = v0B + (a0B - v0B) * 0.5f;
                bool s0B = (v0B >= 1.0f); if (s0B) v0B = 0.f;
                v1B = v1B + (a1B - v1B) * 0.5f;
                bool s1B = (v1B >= 1.0f); if (s1B) v1B = 0.f;
                unsigned B0A = __ballot_sync(0xffffffffu, s0A);
                unsigned B1A = __ballot_sync(0xffffffffu, s1A);
                unsigned B0B = __ballot_sync(0xffffffffu, s0B);
                unsigned B1B = __ballot_sync(0xffffffffu, s1B);
                bool gA = (amask >> ((pp) * 4 + t)) & 1u;
                bool gB = (amask >> ((pp + 1) * 4 + t)) & 1u;
                if (!gA) { B0A = 0u; B1A = 0u; }
                if (!gB) { B0B = 0u; B1B = 0u; }
                if (lane == 0) {
                    *(uint2*)&g_y_cmask[(size_t)colA * 16 + 2 * h] = make_uint2(B0A, B1A);
                    *(uint2*)&g_y_cmask[(size_t)(colA + 1) * 16 + 2 * h] = make_uint2(B0B, B1B);
                }
            }
        }
    }
}

// ---------------- K3: proj GEMM — warp-per-column, high-MLP gather -------
__global__ __launch_bounds__(512) void proj_kernel(float* __restrict__ out) {
    int tid = threadIdx.x;
    int lane = tid & 31, warp = tid >> 5;
    int bid = blockIdx.x;
    int ng = bid & 63;
    int b = (bid >> 6) & 15;
    int t = bid >> 10;
    int n0 = ng * 16;

    __shared__ float stage[512 * 17];

    int n = n0 + warp;
    size_t colbase = (((size_t)(t * BB + b)) * NN + n) * 16;
    unsigned mword = (lane < 16) ? g_y_cmask[colbase + lane] : 0u;

    float acc[16];
#pragma unroll
    for (int m = 0; m < 16; m++) acc[m] = g_bp[m * 32 + lane];

#pragma unroll
    for (int w16 = 0; w16 < 16; w16++) {
        unsigned m = __shfl_sync(0xffffffffu, mword, w16);
        int base = w16 * 32;
        while (m) {
            int c = base + __ffs(m) - 1;
            m &= m - 1;
            const float* row = g_Wp + c * CC;
#pragma unroll
            for (int mm = 0; mm < 16; mm++) acc[mm] += row[mm * 32 + lane];
        }
    }

#pragma unroll
    for (int mm = 0; mm < 16; mm++) stage[(mm * 32 + lane) * 17 + warp] = acc[mm];
    __syncthreads();

    size_t obase = ((size_t)(t * BB + b)) * CC * NN + n0;
#pragma unroll
    for (int r = 0; r < 16; r++) {
        int idx = r * 512 + tid;
        int d = idx >> 4, jj = idx & 15;
        out[obase + (size_t)d * NN + jj] = stage[d * 17 + jj];
    }
}

// ---------------- launch ----------------
extern "C" void kernel_launch(void* const* d_in, const int* in_sizes, int n_in,
                              void* d_out, int out_size) {
    const float* x      = (const float*)d_in[0];
    const float* q_w    = (const float*)d_in[1];
    const float* q_g    = (const float*)d_in[2];
    const float* q_b    = (const float*)d_in[3];
    const float* q_m    = (const float*)d_in[4];
    const float* q_v    = (const float*)d_in[5];
    const float* k_w    = (const float*)d_in[6];
    const float* k_g    = (const float*)d_in[7];
    const float* k_b    = (const float*)d_in[8];
    const float* k_m    = (const float*)d_in[9];
    const float* k_v    = (const float*)d_in[10];
    const float* p_w    = (const float*)d_in[11];
    const float* p_bias = (const float*)d_in[12];
    const float* p_g    = (const float*)d_in[13];
    const float* p_b    = (const float*)d_in[14];
    const float* p_m    = (const float*)d_in[15];
    const float* p_v    = (const float*)d_in[16];

    float* out = (float*)d_out;
    const size_t Y_ELEMS = (size_t)TT * BB * CC * NN;
    const size_t A_ELEMS = (size_t)TT * BB * NHEADS * NN;

    float* attn_ptr;
    if ((size_t)out_size >= Y_ELEMS + A_ELEMS) {
        attn_ptr = out + Y_ELEMS;
    } else {
        void* p = nullptr;
        cudaGetSymbolAddress(&p, g_attn_fallback);
        attn_ptr = (float*)p;
    }

    cudaFuncSetAttribute(qk_kernel, cudaFuncAttributeMaxDynamicSharedMemorySize, SMEM_QK_SZ);

    prep_all_kernel<<<1024, 512>>>(q_w, q_g, q_b, q_m, q_v,
                                   k_w, k_g, k_b, k_m, k_v,
                                   p_w, p_bias, p_g, p_b, p_m, p_v);
    lif_x_kernel<<<16 * 16 * 32, 1024>>>(x);
    list_kernel<<<8192, 256>>>();
    qk_kernel<<<NHEADS * 128, 1024, SMEM_QK_SZ>>>(attn_ptr);
    proj_kernel<<<TT * BB * 64, 512>>>(out);
}